// round 6
// baseline (speedup 1.0000x reference)
#include <cuda_runtime.h>
#include <cuda_fp16.h>
#include <cstdint>

#define NTHREADS 256
#define NBLOCKS  296

// ---------------- PTX helpers ----------------
__device__ __forceinline__ uint32_t smem_u32(const void* p) {
    uint32_t a;
    asm("{ .reg .u64 t; cvta.to.shared.u64 t, %1; cvt.u32.u64 %0, t; }" : "=r"(a) : "l"(p));
    return a;
}
__device__ __forceinline__ void ldmx2(uint32_t& r0, uint32_t& r1, uint32_t addr) {
    asm volatile("ldmatrix.sync.aligned.m8n8.x2.shared.b16 {%0,%1}, [%2];"
                 : "=r"(r0), "=r"(r1) : "r"(addr));
}
__device__ __forceinline__ void ldmx4(uint32_t& r0, uint32_t& r1, uint32_t& r2, uint32_t& r3,
                                      uint32_t addr) {
    asm volatile("ldmatrix.sync.aligned.m8n8.x4.shared.b16 {%0,%1,%2,%3}, [%4];"
                 : "=r"(r0), "=r"(r1), "=r"(r2), "=r"(r3) : "r"(addr));
}
__device__ __forceinline__ void mma_k8(float* d, uint32_t a0, uint32_t a1, uint32_t b0) {
    asm volatile("mma.sync.aligned.m16n8k8.row.col.f32.f16.f16.f32 "
                 "{%0,%1,%2,%3}, {%4,%5}, {%6}, {%0,%1,%2,%3};"
                 : "+f"(d[0]), "+f"(d[1]), "+f"(d[2]), "+f"(d[3])
                 : "r"(a0), "r"(a1), "r"(b0));
}
__device__ __forceinline__ void mma_k16(float* d, uint32_t a0, uint32_t a1, uint32_t a2,
                                        uint32_t a3, uint32_t b0, uint32_t b1) {
    asm volatile("mma.sync.aligned.m16n8k16.row.col.f32.f16.f16.f32 "
                 "{%0,%1,%2,%3}, {%4,%5,%6,%7}, {%8,%9}, {%0,%1,%2,%3};"
                 : "+f"(d[0]), "+f"(d[1]), "+f"(d[2]), "+f"(d[3])
                 : "r"(a0), "r"(a1), "r"(a2), "r"(a3), "r"(b0), "r"(b1));
}
__device__ __forceinline__ uint32_t pack_h2(float x, float y) {
    __half2 h = __floats2half2_rn(x, y);          // low half = x
    return *reinterpret_cast<uint32_t*>(&h);
}

// ---------------- shared memory (dynamic, ~58 KB) ----------------
struct SmemT {
    __align__(16) uint8_t w2t[128 * 256];      // W2^T [n][k] half, swizzled (32 KB)
    __align__(16) __half  w1t[128 * 8];        // W1^T (+b1 in k7)            (2 KB)
    __align__(16) __half  inv[2][128 * 8];     // invariants, double-buffered (4 KB)
    __align__(16) float   scal[2][128 * 8];    // {a,b,c,d,r00,r01}, dbl-buf  (8 KB)
    __align__(16) float   w3[128 * 4];         //                             (2 KB)
    __align__(16) float   part[2][2 * 128 * 4];// layer-3 partials, dbl-buf   (8 KB)
    float b2[128];
    float b3[4];
};

__device__ __forceinline__ void compute_inv(SmemT* sm, int p, int row, float4 f) {
    const float a = f.x, b = f.y, c = f.z, d = f.w;
    const float t0 = a + d, t1 = b - c, t2 = a - d, t3 = b + c;
    const float pp = sqrtf(t0*t0 + t1*t1);
    const float qq = sqrtf(t2*t2 + t3*t3);
    const float i0 = 0.5f*(pp + qq) - 1.f;
    const float i1 = 0.5f*fabsf(pp - qq) - 1.f;
    const float i2 = a*a + c*c - 1.f;
    const float i3 = a*b + c*d;          // == i4
    const float i5 = b*b + d*d - 1.f;
    const float i6 = a*d - b*c - 1.f;
    const float rp  = 1.f / pp;
    const float r00 = t0 * rp, r01 = t1 * rp;

    uint4 u;
    u.x = pack_h2(i0, i1);
    u.y = pack_h2(i2, i3);
    u.z = pack_h2(i3, i5);
    u.w = pack_h2(i6, 1.0f);             // k7 = 1.0 (bias input)
    reinterpret_cast<uint4*>(sm->inv[p])[row] = u;

    float4* s = reinterpret_cast<float4*>(sm->scal[p] + row * 8);
    s[0] = f;
    s[1] = make_float4(r00, r01, 0.f, 0.f);
}

__global__ __launch_bounds__(NTHREADS, 2)
void defcorr_mma(const float* __restrict__ Fg,
                 const float* __restrict__ W1, const float* __restrict__ b1,
                 const float* __restrict__ W2, const float* __restrict__ b2,
                 const float* __restrict__ W3, const float* __restrict__ b3,
                 float* __restrict__ out, int n)
{
    extern __shared__ char dsm[];
    SmemT* sm = reinterpret_cast<SmemT*>(dsm);

    const int tid  = threadIdx.x;
    const int lane = tid & 31;
    const int warp = tid >> 5;
    const int rg   = warp >> 1;               // row group: 32 rows each
    const int ch   = warp & 1;                // column half: 64 cols each
    const int warpm0 = rg * 32;

    // ---------- stage weights (once) ----------
    for (int i = tid; i < 128 * 128; i += NTHREADS) {
        const int nn = i >> 7, k = i & 127;
        const int c  = k >> 3;
        const int cs = (c & 8) | ((c ^ nn) & 7);
        const uint32_t off = (uint32_t)nn * 256u + (uint32_t)cs * 16u + (uint32_t)(k & 7) * 2u;
        *reinterpret_cast<__half*>(sm->w2t + off) = __float2half(W2[k * 128 + nn]);
    }
    for (int i = tid; i < 128 * 8; i += NTHREADS) {
        const int nn = i >> 3, k = i & 7;
        sm->w1t[i] = __float2half(k < 7 ? W1[k * 128 + nn] : b1[nn]);
    }
    for (int i = tid; i < 128 * 4; i += NTHREADS) sm->w3[i] = W3[i];
    for (int i = tid; i < 128;     i += NTHREADS) sm->b2[i] = b2[i];
    if (tid < 4) sm->b3[tid] = b3[tid];

    const uint32_t uW2  = smem_u32(sm->w2t);
    const uint32_t uW1  = smem_u32(sm->w1t);
    const uint32_t uInv = smem_u32(sm->inv[0]);

    // per-lane layer-2 ldmatrix address components
    const int rowPart = ((lane >> 4) << 3) | (lane & 7);
    const int kSel    = (lane >> 3) & 1;
    const uint32_t bAddrBase  = uW2 + (uint32_t)rowPart * 256u + (uint32_t)(ch * 4) * 4096u;
    const uint32_t w1AddrBase = uW1 + (uint32_t)(lane & 15) * 16u;

    const int ntiles = (n + 127) >> 7;

    // ---------- prologue: invariants for first tile into buffer 0 ----------
    if (tid < 128 && blockIdx.x < ntiles) {
        const int elem = blockIdx.x * 128 + tid;
        float4 f = make_float4(1.f, 0.f, 0.f, 1.f);
        if (elem < n) f = reinterpret_cast<const float4*>(Fg)[elem];
        compute_inv(sm, 0, tid, f);
    }
    __syncthreads();

    int p = 0;
    for (int tile = blockIdx.x; tile < ntiles; tile += gridDim.x) {
        const int ntile = tile + gridDim.x;

        // ---------- prefetch next tile's F early (hides LDG behind MMA) ----------
        float4 fnx = make_float4(1.f, 0.f, 0.f, 1.f);
        if (tid < 128 && ntile < ntiles) {
            const int e = ntile * 128 + tid;
            if (e < n) fnx = reinterpret_cast<const float4*>(Fg)[e];
        }

        // ---------- A-inputs for layer 1 (reads inv[p]) ----------
        const uint32_t uInvP = uInv + (uint32_t)p * 2048u;
        uint32_t ai[2][2];
        ldmx2(ai[0][0], ai[0][1], uInvP + (uint32_t)(warpm0      + (lane & 15)) * 16u);
        ldmx2(ai[1][0], ai[1][1], uInvP + (uint32_t)(warpm0 + 16 + (lane & 15)) * 16u);

        // ---------- fused layer1 + layer2, per k-step ----------
        float d2[16][4];
        #pragma unroll
        for (int t = 0; t < 16; ++t) { d2[t][0] = d2[t][1] = d2[t][2] = d2[t][3] = 0.f; }

        #pragma unroll
        for (int s = 0; s < 8; ++s) {
            uint32_t bb0, bb1;
            ldmx2(bb0, bb1, w1AddrBase + (uint32_t)(s * 16) * 16u);

            uint32_t pk[2][4];
            #pragma unroll
            for (int t = 0; t < 2; ++t) {
                float dA[4] = {0.f, 0.f, 0.f, 0.f};
                float dB[4] = {0.f, 0.f, 0.f, 0.f};
                mma_k8(dA, ai[t][0], ai[t][1], bb0);
                mma_k8(dB, ai[t][0], ai[t][1], bb1);
                pk[t][0] = pack_h2(fmaxf(dA[0], 0.f), fmaxf(dA[1], 0.f));
                pk[t][1] = pack_h2(fmaxf(dA[2], 0.f), fmaxf(dA[3], 0.f));
                pk[t][2] = pack_h2(fmaxf(dB[0], 0.f), fmaxf(dB[1], 0.f));
                pk[t][3] = pack_h2(fmaxf(dB[2], 0.f), fmaxf(dB[3], 0.f));
            }

            const int c  = 2*s + kSel;
            const int cs = (c & 8) | ((c ^ rowPart) & 7);
            #pragma unroll
            for (int j = 0; j < 4; ++j) {
                uint32_t br0, br1, br2, br3;
                ldmx4(br0, br1, br2, br3,
                      bAddrBase + (uint32_t)(j * 4096) + (uint32_t)cs * 16u);
                mma_k16(d2[2*j],     pk[0][0], pk[0][1], pk[0][2], pk[0][3], br0, br1);
                mma_k16(d2[2*j+1],   pk[0][0], pk[0][1], pk[0][2], pk[0][3], br2, br3);
                mma_k16(d2[8+2*j],   pk[1][0], pk[1][1], pk[1][2], pk[1][3], br0, br1);
                mma_k16(d2[8+2*j+1], pk[1][0], pk[1][1], pk[1][2], pk[1][3], br2, br3);
            }
        }

        // ---------- layer 3 partials over this warp's 64 columns ----------
        float pacc[4][4];
        #pragma unroll
        for (int i = 0; i < 4; ++i) { pacc[i][0]=pacc[i][1]=pacc[i][2]=pacc[i][3]=0.f; }

        #pragma unroll
        for (int t = 0; t < 2; ++t) {
            #pragma unroll
            for (int jl = 0; jl < 8; ++jl) {
                const int n0 = ch*64 + jl*8 + (lane & 3)*2;
                const float bb0 = sm->b2[n0], bb1 = sm->b2[n0 + 1];
                const float* dd = d2[t*8 + jl];
                const float hA0 = fmaxf(dd[0] + bb0, 0.f);
                const float hA1 = fmaxf(dd[1] + bb1, 0.f);
                const float hB0 = fmaxf(dd[2] + bb0, 0.f);
                const float hB1 = fmaxf(dd[3] + bb1, 0.f);
                const float4 w0 = reinterpret_cast<const float4*>(sm->w3)[n0];
                const float4 w1 = reinterpret_cast<const float4*>(sm->w3)[n0 + 1];
                pacc[t*2+0][0] = fmaf(hA0, w0.x, fmaf(hA1, w1.x, pacc[t*2+0][0]));
                pacc[t*2+0][1] = fmaf(hA0, w0.y, fmaf(hA1, w1.y, pacc[t*2+0][1]));
                pacc[t*2+0][2] = fmaf(hA0, w0.z, fmaf(hA1, w1.z, pacc[t*2+0][2]));
                pacc[t*2+0][3] = fmaf(hA0, w0.w, fmaf(hA1, w1.w, pacc[t*2+0][3]));
                pacc[t*2+1][0] = fmaf(hB0, w0.x, fmaf(hB1, w1.x, pacc[t*2+1][0]));
                pacc[t*2+1][1] = fmaf(hB0, w0.y, fmaf(hB1, w1.y, pacc[t*2+1][1]));
                pacc[t*2+1][2] = fmaf(hB0, w0.z, fmaf(hB1, w1.z, pacc[t*2+1][2]));
                pacc[t*2+1][3] = fmaf(hB0, w0.w, fmaf(hB1, w1.w, pacc[t*2+1][3]));
            }
        }
        #pragma unroll
        for (int i = 0; i < 4; ++i) {
            #pragma unroll
            for (int k2 = 0; k2 < 4; ++k2) {
                pacc[i][k2] += __shfl_xor_sync(0xffffffffu, pacc[i][k2], 1);
                pacc[i][k2] += __shfl_xor_sync(0xffffffffu, pacc[i][k2], 2);
            }
        }
        if ((lane & 3) == 0) {
            #pragma unroll
            for (int t = 0; t < 2; ++t) {
                #pragma unroll
                for (int rr = 0; rr < 2; ++rr) {
                    const int row = warpm0 + t*16 + (lane >> 2) + rr*8;
                    reinterpret_cast<float4*>(sm->part[p])[ch*128 + row] =
                        make_float4(pacc[t*2+rr][0], pacc[t*2+rr][1],
                                    pacc[t*2+rr][2], pacc[t*2+rr][3]);
                }
            }
        }

        // ---------- invariants for next tile (other buffer; overlaps MMA stragglers) ----------
        if (tid < 128 && ntile < ntiles) compute_inv(sm, p ^ 1, tid, fnx);

        __syncthreads();   // single barrier: covers part[p] and inv/scal[p^1]

        // ---------- final epilogue: combine halves, rotate, store ----------
        if (tid < 128) {
            const int row  = tid;
            const int elem = tile * 128 + row;
            if (elem < n) {
                const float4 pa = reinterpret_cast<const float4*>(sm->part[p])[row];
                const float4 pb = reinterpret_cast<const float4*>(sm->part[p])[128 + row];
                const float o0 = pa.x + pb.x + sm->b3[0];
                const float o1 = pa.y + pb.y + sm->b3[1];
                const float o2 = pa.z + pb.z + sm->b3[2];
                const float o3 = pa.w + pb.w + sm->b3[3];
                const float4* s = reinterpret_cast<const float4*>(sm->scal[p] + row * 8);
                const float4 fv = s[0];
                const float4 rv = s[1];
                const float x00 = o0, x01 = 0.5f * (o1 + o2), x11 = o3;
                const float r00 = rv.x, r01 = rv.y;
                float4 ov;
                ov.x =  r00*x00 + r01*x01 + fv.x;
                ov.y =  r00*x01 + r01*x11 + fv.y;
                ov.z = -r01*x00 + r00*x01 + fv.z;
                ov.w = -r01*x01 + r00*x11 + fv.w;
                reinterpret_cast<float4*>(out)[elem] = ov;
            }
        }
        p ^= 1;
    }
}

extern "C" void kernel_launch(void* const* d_in, const int* in_sizes, int n_in,
                              void* d_out, int out_size)
{
    const float* F  = (const float*)d_in[0];
    const float* W1 = (const float*)d_in[1];
    const float* b1 = (const float*)d_in[2];
    const float* W2 = (const float*)d_in[3];
    const float* b2 = (const float*)d_in[4];
    const float* W3 = (const float*)d_in[5];
    const float* b3 = (const float*)d_in[6];
    float* out = (float*)d_out;

    const int n = in_sizes[0] / 4;   // number of 2x2 matrices

    const size_t smem_bytes = sizeof(SmemT);
    cudaFuncSetAttribute(defcorr_mma,
                         cudaFuncAttributeMaxDynamicSharedMemorySize, (int)smem_bytes);

    defcorr_mma<<<NBLOCKS, NTHREADS, smem_bytes>>>(F, W1, b1, W2, b2, W3, b3, out, n);
}

// round 7
// speedup vs baseline: 1.1720x; 1.1720x over previous
#include <cuda_runtime.h>
#include <cuda_fp16.h>
#include <cstdint>

#define NTHREADS 256
#define NBLOCKS  296

// ---------------- PTX helpers ----------------
__device__ __forceinline__ uint32_t smem_u32(const void* p) {
    uint32_t a;
    asm("{ .reg .u64 t; cvta.to.shared.u64 t, %1; cvt.u32.u64 %0, t; }" : "=r"(a) : "l"(p));
    return a;
}
__device__ __forceinline__ void ldmx2(uint32_t& r0, uint32_t& r1, uint32_t addr) {
    asm volatile("ldmatrix.sync.aligned.m8n8.x2.shared.b16 {%0,%1}, [%2];"
                 : "=r"(r0), "=r"(r1) : "r"(addr));
}
__device__ __forceinline__ void ldmx4(uint32_t& r0, uint32_t& r1, uint32_t& r2, uint32_t& r3,
                                      uint32_t addr) {
    asm volatile("ldmatrix.sync.aligned.m8n8.x4.shared.b16 {%0,%1,%2,%3}, [%4];"
                 : "=r"(r0), "=r"(r1), "=r"(r2), "=r"(r3) : "r"(addr));
}
__device__ __forceinline__ void mma_k8(float* d, uint32_t a0, uint32_t a1, uint32_t b0) {
    asm volatile("mma.sync.aligned.m16n8k8.row.col.f32.f16.f16.f32 "
                 "{%0,%1,%2,%3}, {%4,%5}, {%6}, {%0,%1,%2,%3};"
                 : "+f"(d[0]), "+f"(d[1]), "+f"(d[2]), "+f"(d[3])
                 : "r"(a0), "r"(a1), "r"(b0));
}
__device__ __forceinline__ void mma_k16(float* d, uint32_t a0, uint32_t a1, uint32_t a2,
                                        uint32_t a3, uint32_t b0, uint32_t b1) {
    asm volatile("mma.sync.aligned.m16n8k16.row.col.f32.f16.f16.f32 "
                 "{%0,%1,%2,%3}, {%4,%5,%6,%7}, {%8,%9}, {%0,%1,%2,%3};"
                 : "+f"(d[0]), "+f"(d[1]), "+f"(d[2]), "+f"(d[3])
                 : "r"(a0), "r"(a1), "r"(a2), "r"(a3), "r"(b0), "r"(b1));
}
__device__ __forceinline__ uint32_t pack_h2(float x, float y) {
    __half2 h = __floats2half2_rn(x, y);          // low half = x
    return *reinterpret_cast<uint32_t*>(&h);
}
__device__ __forceinline__ uint32_t pack_relu_h2(float x, float y) {
    return pack_h2(fmaxf(x, 0.f), fmaxf(y, 0.f));
}

// ---------------- shared memory (dynamic, ~58 KB) ----------------
struct SmemT {
    __align__(16) uint8_t w2t[128 * 256];      // W2^T [n][k] half, swizzled (32 KB)
    __align__(16) __half  w1t[128 * 8];        // W1^T (+b1 in k7)            (2 KB)
    __align__(16) __half  inv[2][128 * 8];     // invariants, double-buffered (4 KB)
    __align__(16) float   scal[2][128 * 8];    // {a,b,c,d,r00,r01}, dbl-buf  (8 KB)
    __align__(16) float   w3[128 * 4];         // staging for W3 frag preload (2 KB)
    __align__(16) float   part[2][2 * 128 * 4];// layer-3 partials, dbl-buf   (8 KB)
    float b2[128];
    float b3[4];
};

__device__ __forceinline__ void compute_inv(SmemT* sm, int p, int row, float4 f) {
    const float a = f.x, b = f.y, c = f.z, d = f.w;
    const float t0 = a + d, t1 = b - c, t2 = a - d, t3 = b + c;
    const float pp = sqrtf(t0*t0 + t1*t1);
    const float qq = sqrtf(t2*t2 + t3*t3);
    const float i0 = 0.5f*(pp + qq) - 1.f;
    const float i1 = 0.5f*fabsf(pp - qq) - 1.f;
    const float i2 = a*a + c*c - 1.f;
    const float i3 = a*b + c*d;          // == i4
    const float i5 = b*b + d*d - 1.f;
    const float i6 = a*d - b*c - 1.f;
    const float rp  = 1.f / pp;
    const float r00 = t0 * rp, r01 = t1 * rp;

    uint4 u;
    u.x = pack_h2(i0, i1);
    u.y = pack_h2(i2, i3);
    u.z = pack_h2(i3, i5);
    u.w = pack_h2(i6, 1.0f);             // k7 = 1.0 (bias input)
    reinterpret_cast<uint4*>(sm->inv[p])[row] = u;

    float4* s = reinterpret_cast<float4*>(sm->scal[p] + row * 8);
    s[0] = f;
    s[1] = make_float4(r00, r01, 0.f, 0.f);
}

__global__ __launch_bounds__(NTHREADS, 2)
void defcorr_mma(const float* __restrict__ Fg,
                 const float* __restrict__ W1, const float* __restrict__ b1,
                 const float* __restrict__ W2, const float* __restrict__ b2,
                 const float* __restrict__ W3, const float* __restrict__ b3,
                 float* __restrict__ out, int n)
{
    extern __shared__ char dsm[];
    SmemT* sm = reinterpret_cast<SmemT*>(dsm);

    const int tid  = threadIdx.x;
    const int lane = tid & 31;
    const int warp = tid >> 5;
    const int rg   = warp >> 1;               // row group: 32 rows each
    const int ch   = warp & 1;                // column half: 64 cols each
    const int warpm0 = rg * 32;

    // ---------- stage weights (once) ----------
    for (int i = tid; i < 128 * 128; i += NTHREADS) {
        const int nn = i >> 7, k = i & 127;
        const int c  = k >> 3;
        const int cs = (c & 8) | ((c ^ nn) & 7);
        const uint32_t off = (uint32_t)nn * 256u + (uint32_t)cs * 16u + (uint32_t)(k & 7) * 2u;
        *reinterpret_cast<__half*>(sm->w2t + off) = __float2half(W2[k * 128 + nn]);
    }
    for (int i = tid; i < 128 * 8; i += NTHREADS) {
        const int nn = i >> 3, k = i & 7;
        sm->w1t[i] = __float2half(k < 7 ? W1[k * 128 + nn] : b1[nn]);
    }
    for (int i = tid; i < 128 * 4; i += NTHREADS) sm->w3[i] = W3[i];
    for (int i = tid; i < 128;     i += NTHREADS) sm->b2[i] = b2[i];
    if (tid < 4) sm->b3[tid] = b3[tid];

    const uint32_t uW2  = smem_u32(sm->w2t);
    const uint32_t uW1  = smem_u32(sm->w1t);
    const uint32_t uInv = smem_u32(sm->inv[0]);

    // per-lane layer-2 ldmatrix address components
    const int rowPart = ((lane >> 4) << 3) | (lane & 7);
    const int kSel    = (lane >> 3) & 1;
    const uint32_t bAddrBase  = uW2 + (uint32_t)rowPart * 256u + (uint32_t)(ch * 4) * 4096u;
    const uint32_t w1AddrBase = uW1 + (uint32_t)(lane & 15) * 16u;

    __syncthreads();   // w3/b2 staged before fragment preload

    // ---------- preload layer-3 W3 B-fragments (persistent, 8 regs) ----------
    // mma m16n8k16 B frag: b0 -> (k=(lane&3)*2+{0,1}, n=lane>>2), b1 -> k+8.
    // n (output) 0..3 real, 4..7 zero pad. k global = ch*64 + s3*16 + klocal.
    uint32_t w3b[4][2];
    {
        const int nn = lane >> 2;
        #pragma unroll
        for (int s3 = 0; s3 < 4; ++s3) {
            const int k0 = ch*64 + s3*16 + (lane & 3)*2;
            if (nn < 4) {
                w3b[s3][0] = pack_h2(sm->w3[k0*4 + nn],       sm->w3[(k0+1)*4 + nn]);
                w3b[s3][1] = pack_h2(sm->w3[(k0+8)*4 + nn],   sm->w3[(k0+9)*4 + nn]);
            } else {
                w3b[s3][0] = 0u; w3b[s3][1] = 0u;
            }
        }
    }

    const int ntiles = (n + 127) >> 7;

    // ---------- prologue: invariants for first tile into buffer 0 ----------
    if (tid < 128 && blockIdx.x < ntiles) {
        const int elem = blockIdx.x * 128 + tid;
        float4 f = make_float4(1.f, 0.f, 0.f, 1.f);
        if (elem < n) f = reinterpret_cast<const float4*>(Fg)[elem];
        compute_inv(sm, 0, tid, f);
    }
    __syncthreads();

    int p = 0;
    for (int tile = blockIdx.x; tile < ntiles; tile += gridDim.x) {
        const int ntile = tile + gridDim.x;

        // ---------- prefetch next tile's F early (hides LDG behind MMA) ----------
        float4 fnx = make_float4(1.f, 0.f, 0.f, 1.f);
        if (tid < 128 && ntile < ntiles) {
            const int e = ntile * 128 + tid;
            if (e < n) fnx = reinterpret_cast<const float4*>(Fg)[e];
        }

        // ---------- A-inputs for layer 1 (reads inv[p]) ----------
        const uint32_t uInvP = uInv + (uint32_t)p * 2048u;
        uint32_t ai[2][2];
        ldmx2(ai[0][0], ai[0][1], uInvP + (uint32_t)(warpm0      + (lane & 15)) * 16u);
        ldmx2(ai[1][0], ai[1][1], uInvP + (uint32_t)(warpm0 + 16 + (lane & 15)) * 16u);

        // ---------- init layer-2 accumulators with b2 (folds bias into GEMM) ----------
        float d2[16][4];
        #pragma unroll
        for (int jl = 0; jl < 8; ++jl) {
            const float2 bb = *reinterpret_cast<const float2*>(
                sm->b2 + ch*64 + jl*8 + (lane & 3)*2);
            d2[jl][0]   = bb.x; d2[jl][1]   = bb.y; d2[jl][2]   = bb.x; d2[jl][3]   = bb.y;
            d2[8+jl][0] = bb.x; d2[8+jl][1] = bb.y; d2[8+jl][2] = bb.x; d2[8+jl][3] = bb.y;
        }

        // ---------- fused layer1 + layer2, per k-step ----------
        #pragma unroll
        for (int s = 0; s < 8; ++s) {
            uint32_t bb0, bb1;
            ldmx2(bb0, bb1, w1AddrBase + (uint32_t)(s * 16) * 16u);

            uint32_t pk[2][4];
            #pragma unroll
            for (int t = 0; t < 2; ++t) {
                float dA[4] = {0.f, 0.f, 0.f, 0.f};
                float dB[4] = {0.f, 0.f, 0.f, 0.f};
                mma_k8(dA, ai[t][0], ai[t][1], bb0);
                mma_k8(dB, ai[t][0], ai[t][1], bb1);
                pk[t][0] = pack_relu_h2(dA[0], dA[1]);
                pk[t][1] = pack_relu_h2(dA[2], dA[3]);
                pk[t][2] = pack_relu_h2(dB[0], dB[1]);
                pk[t][3] = pack_relu_h2(dB[2], dB[3]);
            }

            const int c  = 2*s + kSel;
            const int cs = (c & 8) | ((c ^ rowPart) & 7);
            #pragma unroll
            for (int j = 0; j < 4; ++j) {
                uint32_t br0, br1, br2, br3;
                ldmx4(br0, br1, br2, br3,
                      bAddrBase + (uint32_t)(j * 4096) + (uint32_t)cs * 16u);
                mma_k16(d2[2*j],     pk[0][0], pk[0][1], pk[0][2], pk[0][3], br0, br1);
                mma_k16(d2[2*j+1],   pk[0][0], pk[0][1], pk[0][2], pk[0][3], br2, br3);
                mma_k16(d2[8+2*j],   pk[1][0], pk[1][1], pk[1][2], pk[1][3], br0, br1);
                mma_k16(d2[8+2*j+1], pk[1][0], pk[1][1], pk[1][2], pk[1][3], br2, br3);
            }
        }

        // ---------- layer 3 as MMA: relu(d2) fragments -> o3 (n=8, cols 4..7 pad) ----------
        float o3[2][4];
        o3[0][0]=o3[0][1]=o3[0][2]=o3[0][3]=0.f;
        o3[1][0]=o3[1][1]=o3[1][2]=o3[1][3]=0.f;
        #pragma unroll
        for (int s3 = 0; s3 < 4; ++s3) {
            const int j0 = 2*s3, j1 = 2*s3 + 1;
            #pragma unroll
            for (int t = 0; t < 2; ++t) {
                const float* dj0 = d2[t*8 + j0];
                const float* dj1 = d2[t*8 + j1];
                const uint32_t a0 = pack_relu_h2(dj0[0], dj0[1]);
                const uint32_t a1 = pack_relu_h2(dj0[2], dj0[3]);
                const uint32_t a2 = pack_relu_h2(dj1[0], dj1[1]);
                const uint32_t a3 = pack_relu_h2(dj1[2], dj1[3]);
                mma_k16(o3[t], a0, a1, a2, a3, w3b[s3][0], w3b[s3][1]);
            }
        }

        // ---------- write layer-3 partials (only lanes with n<4 hold real data) ----------
        // o3[t]: [0]=(m, n=(lane&3)*2), [1]=n+1, [2]=(m+8, n), [3]=(m+8, n+1)
        if ((lane & 3) < 2) {
            #pragma unroll
            for (int t = 0; t < 2; ++t) {
                const int row0 = warpm0 + t*16 + (lane >> 2);
                float2* p0 = reinterpret_cast<float2*>(
                    sm->part[p] + (ch*128 + row0) * 4) + (lane & 3);
                float2* p1 = reinterpret_cast<float2*>(
                    sm->part[p] + (ch*128 + row0 + 8) * 4) + (lane & 3);
                *p0 = make_float2(o3[t][0], o3[t][1]);
                *p1 = make_float2(o3[t][2], o3[t][3]);
            }
        }

        // ---------- invariants for next tile (other buffer; overlaps MMA stragglers) ----------
        if (tid < 128 && ntile < ntiles) compute_inv(sm, p ^ 1, tid, fnx);

        __syncthreads();   // single barrier: covers part[p] and inv/scal[p^1]

        // ---------- final epilogue: combine halves, rotate, store ----------
        if (tid < 128) {
            const int row  = tid;
            const int elem = tile * 128 + row;
            if (elem < n) {
                const float4 pa = reinterpret_cast<const float4*>(sm->part[p])[row];
                const float4 pb = reinterpret_cast<const float4*>(sm->part[p])[128 + row];
                const float o0 = pa.x + pb.x + sm->b3[0];
                const float o1 = pa.y + pb.y + sm->b3[1];
                const float o2 = pa.z + pb.z + sm->b3[2];
                const float o3v = pa.w + pb.w + sm->b3[3];
                const float4* s = reinterpret_cast<const float4*>(sm->scal[p] + row * 8);
                const float4 fv = s[0];
                const float4 rv = s[1];
                const float x00 = o0, x01 = 0.5f * (o1 + o2), x11 = o3v;
                const float r00 = rv.x, r01 = rv.y;
                float4 ov;
                ov.x =  r00*x00 + r01*x01 + fv.x;
                ov.y =  r00*x01 + r01*x11 + fv.y;
                ov.z = -r01*x00 + r00*x01 + fv.z;
                ov.w = -r01*x01 + r00*x11 + fv.w;
                reinterpret_cast<float4*>(out)[elem] = ov;
            }
        }
        p ^= 1;
    }
}

extern "C" void kernel_launch(void* const* d_in, const int* in_sizes, int n_in,
                              void* d_out, int out_size)
{
    const float* F  = (const float*)d_in[0];
    const float* W1 = (const float*)d_in[1];
    const float* b1 = (const float*)d_in[2];
    const float* W2 = (const float*)d_in[3];
    const float* b2 = (const float*)d_in[4];
    const float* W3 = (const float*)d_in[5];
    const float* b3 = (const float*)d_in[6];
    float* out = (float*)d_out;

    const int n = in_sizes[0] / 4;   // number of 2x2 matrices

    const size_t smem_bytes = sizeof(SmemT);
    cudaFuncSetAttribute(defcorr_mma,
                         cudaFuncAttributeMaxDynamicSharedMemorySize, (int)smem_bytes);

    defcorr_mma<<<NBLOCKS, NTHREADS, smem_bytes>>>(F, W1, b1, W2, b2, W3, b3, out, n);
}

// round 8
// speedup vs baseline: 1.2171x; 1.0385x over previous
#include <cuda_runtime.h>
#include <cuda_fp16.h>
#include <cstdint>

#define NTHREADS 256
#define NBLOCKS  296

// ---------------- PTX helpers ----------------
__device__ __forceinline__ uint32_t smem_u32(const void* p) {
    uint32_t a;
    asm("{ .reg .u64 t; cvta.to.shared.u64 t, %1; cvt.u32.u64 %0, t; }" : "=r"(a) : "l"(p));
    return a;
}
__device__ __forceinline__ void ldmx2(uint32_t& r0, uint32_t& r1, uint32_t addr) {
    asm volatile("ldmatrix.sync.aligned.m8n8.x2.shared.b16 {%0,%1}, [%2];"
                 : "=r"(r0), "=r"(r1) : "r"(addr));
}
__device__ __forceinline__ void ldmx4(uint32_t& r0, uint32_t& r1, uint32_t& r2, uint32_t& r3,
                                      uint32_t addr) {
    asm volatile("ldmatrix.sync.aligned.m8n8.x4.shared.b16 {%0,%1,%2,%3}, [%4];"
                 : "=r"(r0), "=r"(r1), "=r"(r2), "=r"(r3) : "r"(addr));
}
// layer-1 MMA with fp16 accumulators: D regs are packed half2 in exactly the
// A-fragment layout required by the layer-2 m16n8k16 MMA.
__device__ __forceinline__ void mma_k8_f16(uint32_t& d0, uint32_t& d1,
                                           uint32_t a0, uint32_t a1, uint32_t b0,
                                           uint32_t zero) {
    asm volatile("mma.sync.aligned.m16n8k8.row.col.f16.f16.f16.f16 "
                 "{%0,%1}, {%2,%3}, {%4}, {%5,%5};"
                 : "=r"(d0), "=r"(d1)
                 : "r"(a0), "r"(a1), "r"(b0), "r"(zero));
}
__device__ __forceinline__ void mma_k16(float* d, uint32_t a0, uint32_t a1, uint32_t a2,
                                        uint32_t a3, uint32_t b0, uint32_t b1) {
    asm volatile("mma.sync.aligned.m16n8k16.row.col.f32.f16.f16.f32 "
                 "{%0,%1,%2,%3}, {%4,%5,%6,%7}, {%8,%9}, {%0,%1,%2,%3};"
                 : "+f"(d[0]), "+f"(d[1]), "+f"(d[2]), "+f"(d[3])
                 : "r"(a0), "r"(a1), "r"(a2), "r"(a3), "r"(b0), "r"(b1));
}
__device__ __forceinline__ uint32_t pack_h2(float x, float y) {
    __half2 h = __floats2half2_rn(x, y);          // low half = x
    return *reinterpret_cast<uint32_t*>(&h);
}
__device__ __forceinline__ uint32_t pack_relu_h2(float x, float y) {
    return pack_h2(fmaxf(x, 0.f), fmaxf(y, 0.f));
}
__device__ __forceinline__ uint32_t relu_h2(uint32_t u) {
    __half2 h = *reinterpret_cast<__half2*>(&u);
    __half2 z = __floats2half2_rn(0.f, 0.f);
    __half2 r = __hmax2(h, z);
    return *reinterpret_cast<uint32_t*>(&r);
}

// ---------------- shared memory (dynamic, ~58 KB) ----------------
struct SmemT {
    __align__(16) uint8_t w2t[128 * 256];      // W2^T [n][k] half, swizzled (32 KB)
    __align__(16) __half  w1t[128 * 8];        // W1^T (+b1 in k7)            (2 KB)
    __align__(16) __half  inv[2][128 * 8];     // invariants, double-buffered (4 KB)
    __align__(16) float   scal[2][128 * 8];    // {a,b,c,d,r00,r01}, dbl-buf  (8 KB)
    __align__(16) float   w3[128 * 4];         // staging for W3 frag preload (2 KB)
    __align__(16) float   part[2][2 * 128 * 4];// layer-3 partials, dbl-buf   (8 KB)
    float b2[128];
    float b3[4];
};

__device__ __forceinline__ void compute_inv(SmemT* sm, int p, int row, float4 f) {
    const float a = f.x, b = f.y, c = f.z, d = f.w;
    const float t0 = a + d, t1 = b - c, t2 = a - d, t3 = b + c;
    const float pp = sqrtf(t0*t0 + t1*t1);
    const float qq = sqrtf(t2*t2 + t3*t3);
    const float i0 = 0.5f*(pp + qq) - 1.f;
    const float i1 = 0.5f*fabsf(pp - qq) - 1.f;
    const float i2 = a*a + c*c - 1.f;
    const float i3 = a*b + c*d;          // == i4
    const float i5 = b*b + d*d - 1.f;
    const float i6 = a*d - b*c - 1.f;
    const float rp  = 1.f / pp;
    const float r00 = t0 * rp, r01 = t1 * rp;

    uint4 u;
    u.x = pack_h2(i0, i1);
    u.y = pack_h2(i2, i3);
    u.z = pack_h2(i3, i5);
    u.w = pack_h2(i6, 1.0f);             // k7 = 1.0 (bias input)
    reinterpret_cast<uint4*>(sm->inv[p])[row] = u;

    float4* s = reinterpret_cast<float4*>(sm->scal[p] + row * 8);
    s[0] = f;
    s[1] = make_float4(r00, r01, 0.f, 0.f);
}

__global__ __launch_bounds__(NTHREADS, 2)
void defcorr_mma(const float* __restrict__ Fg,
                 const float* __restrict__ W1, const float* __restrict__ b1,
                 const float* __restrict__ W2, const float* __restrict__ b2,
                 const float* __restrict__ W3, const float* __restrict__ b3,
                 float* __restrict__ out, int n)
{
    extern __shared__ char dsm[];
    SmemT* sm = reinterpret_cast<SmemT*>(dsm);

    const int tid  = threadIdx.x;
    const int lane = tid & 31;
    const int warp = tid >> 5;
    const int rg   = warp >> 1;               // row group: 32 rows each
    const int ch   = warp & 1;                // column half: 64 cols each
    const int warpm0 = rg * 32;

    // ---------- stage weights (once) ----------
    for (int i = tid; i < 128 * 128; i += NTHREADS) {
        const int nn = i >> 7, k = i & 127;
        const int c  = k >> 3;
        const int cs = (c & 8) | ((c ^ nn) & 7);
        const uint32_t off = (uint32_t)nn * 256u + (uint32_t)cs * 16u + (uint32_t)(k & 7) * 2u;
        *reinterpret_cast<__half*>(sm->w2t + off) = __float2half(W2[k * 128 + nn]);
    }
    for (int i = tid; i < 128 * 8; i += NTHREADS) {
        const int nn = i >> 3, k = i & 7;
        sm->w1t[i] = __float2half(k < 7 ? W1[k * 128 + nn] : b1[nn]);
    }
    for (int i = tid; i < 128 * 4; i += NTHREADS) sm->w3[i] = W3[i];
    for (int i = tid; i < 128;     i += NTHREADS) sm->b2[i] = b2[i];
    if (tid < 4) sm->b3[tid] = b3[tid];

    const uint32_t uW2  = smem_u32(sm->w2t);
    const uint32_t uW1  = smem_u32(sm->w1t);
    const uint32_t uInv = smem_u32(sm->inv[0]);

    // per-lane layer-2 ldmatrix address components
    const int rowPart = ((lane >> 4) << 3) | (lane & 7);
    const int kSel    = (lane >> 3) & 1;
    const uint32_t bAddrBase  = uW2 + (uint32_t)rowPart * 256u + (uint32_t)(ch * 4) * 4096u;
    const uint32_t w1AddrBase = uW1 + (uint32_t)(lane & 15) * 16u;

    __syncthreads();   // weights staged

    // ---------- preload persistent fragments ----------
    // W1 B-fragments: 8 k-steps x 2 regs (constant all kernel)
    uint32_t w1f[8][2];
    #pragma unroll
    for (int s = 0; s < 8; ++s)
        ldmx2(w1f[s][0], w1f[s][1], w1AddrBase + (uint32_t)(s * 16) * 16u);

    // W3 B-fragments: n 0..3 real, 4..7 zero pad; k global = ch*64 + s3*16 + klocal
    uint32_t w3b[4][2];
    {
        const int nn = lane >> 2;
        #pragma unroll
        for (int s3 = 0; s3 < 4; ++s3) {
            const int k0 = ch*64 + s3*16 + (lane & 3)*2;
            if (nn < 4) {
                w3b[s3][0] = pack_h2(sm->w3[k0*4 + nn],       sm->w3[(k0+1)*4 + nn]);
                w3b[s3][1] = pack_h2(sm->w3[(k0+8)*4 + nn],   sm->w3[(k0+9)*4 + nn]);
            } else {
                w3b[s3][0] = 0u; w3b[s3][1] = 0u;
            }
        }
    }

    const int ntiles = (n + 127) >> 7;

    // ---------- prologue: invariants for first tile into buffer 0 ----------
    if (tid < 128 && blockIdx.x < ntiles) {
        const int elem = blockIdx.x * 128 + tid;
        float4 f = make_float4(1.f, 0.f, 0.f, 1.f);
        if (elem < n) f = reinterpret_cast<const float4*>(Fg)[elem];
        compute_inv(sm, 0, tid, f);
    }
    __syncthreads();

    const uint32_t zero = 0u;
    int p = 0;
    for (int tile = blockIdx.x; tile < ntiles; tile += gridDim.x) {
        const int ntile = tile + gridDim.x;

        // ---------- prefetch next tile's F early (hides LDG behind MMA) ----------
        float4 fnx = make_float4(1.f, 0.f, 0.f, 1.f);
        if (tid < 128 && ntile < ntiles) {
            const int e = ntile * 128 + tid;
            if (e < n) fnx = reinterpret_cast<const float4*>(Fg)[e];
        }

        // ---------- A-inputs for layer 1 (reads inv[p]) ----------
        const uint32_t uInvP = uInv + (uint32_t)p * 2048u;
        uint32_t ai[2][2];
        ldmx2(ai[0][0], ai[0][1], uInvP + (uint32_t)(warpm0      + (lane & 15)) * 16u);
        ldmx2(ai[1][0], ai[1][1], uInvP + (uint32_t)(warpm0 + 16 + (lane & 15)) * 16u);

        // ---------- init layer-2 accumulators with b2 (folds bias into GEMM) ----------
        float d2[16][4];
        #pragma unroll
        for (int jl = 0; jl < 8; ++jl) {
            const float2 bb = *reinterpret_cast<const float2*>(
                sm->b2 + ch*64 + jl*8 + (lane & 3)*2);
            d2[jl][0]   = bb.x; d2[jl][1]   = bb.y; d2[jl][2]   = bb.x; d2[jl][3]   = bb.y;
            d2[8+jl][0] = bb.x; d2[8+jl][1] = bb.y; d2[8+jl][2] = bb.x; d2[8+jl][3] = bb.y;
        }

        // ---------- fused layer1 (f16 accum) + layer2, per k-step ----------
        #pragma unroll
        for (int s = 0; s < 8; ++s) {
            uint32_t pk[2][4];
            #pragma unroll
            for (int t = 0; t < 2; ++t) {
                uint32_t u0, u1, u2, u3;
                mma_k8_f16(u0, u1, ai[t][0], ai[t][1], w1f[s][0], zero);
                mma_k8_f16(u2, u3, ai[t][0], ai[t][1], w1f[s][1], zero);
                pk[t][0] = relu_h2(u0);   // (r,   k-lo pair) -> a0
                pk[t][1] = relu_h2(u1);   // (r+8, k-lo pair) -> a1
                pk[t][2] = relu_h2(u2);   // (r,   k-hi pair) -> a2
                pk[t][3] = relu_h2(u3);   // (r+8, k-hi pair) -> a3
            }

            const int c  = 2*s + kSel;
            const int cs = (c & 8) | ((c ^ rowPart) & 7);
            #pragma unroll
            for (int j = 0; j < 4; ++j) {
                uint32_t br0, br1, br2, br3;
                ldmx4(br0, br1, br2, br3,
                      bAddrBase + (uint32_t)(j * 4096) + (uint32_t)cs * 16u);
                mma_k16(d2[2*j],     pk[0][0], pk[0][1], pk[0][2], pk[0][3], br0, br1);
                mma_k16(d2[2*j+1],   pk[0][0], pk[0][1], pk[0][2], pk[0][3], br2, br3);
                mma_k16(d2[8+2*j],   pk[1][0], pk[1][1], pk[1][2], pk[1][3], br0, br1);
                mma_k16(d2[8+2*j+1], pk[1][0], pk[1][1], pk[1][2], pk[1][3], br2, br3);
            }
        }

        // ---------- layer 3 as MMA: relu(d2) fragments -> o3 (n=8, cols 4..7 pad) ----------
        float o3[2][4];
        o3[0][0]=o3[0][1]=o3[0][2]=o3[0][3]=0.f;
        o3[1][0]=o3[1][1]=o3[1][2]=o3[1][3]=0.f;
        #pragma unroll
        for (int s3 = 0; s3 < 4; ++s3) {
            const int j0 = 2*s3, j1 = 2*s3 + 1;
            #pragma unroll
            for (int t = 0; t < 2; ++t) {
                const float* dj0 = d2[t*8 + j0];
                const float* dj1 = d2[t*8 + j1];
                const uint32_t a0 = pack_relu_h2(dj0[0], dj0[1]);
                const uint32_t a1 = pack_relu_h2(dj0[2], dj0[3]);
                const uint32_t a2 = pack_relu_h2(dj1[0], dj1[1]);
                const uint32_t a3 = pack_relu_h2(dj1[2], dj1[3]);
                mma_k16(o3[t], a0, a1, a2, a3, w3b[s3][0], w3b[s3][1]);
            }
        }

        // ---------- write layer-3 partials (only lanes with n<4 hold real data) ----------
        if ((lane & 3) < 2) {
            #pragma unroll
            for (int t = 0; t < 2; ++t) {
                const int row0 = warpm0 + t*16 + (lane >> 2);
                float2* p0 = reinterpret_cast<float2*>(
                    sm->part[p] + (ch*128 + row0) * 4) + (lane & 3);
                float2* p1 = reinterpret_cast<float2*>(
                    sm->part[p] + (ch*128 + row0 + 8) * 4) + (lane & 3);
                *p0 = make_float2(o3[t][0], o3[t][1]);
                *p1 = make_float2(o3[t][2], o3[t][3]);
            }
        }

        // ---------- invariants for next tile (other buffer; overlaps MMA stragglers) ----------
        if (tid < 128 && ntile < ntiles) compute_inv(sm, p ^ 1, tid, fnx);

        __syncthreads();   // single barrier: covers part[p] and inv/scal[p^1]

        // ---------- final epilogue: combine halves, rotate, store ----------
        if (tid < 128) {
            const int row  = tid;
            const int elem = tile * 128 + row;
            if (elem < n) {
                const float4 pa = reinterpret_cast<const float4*>(sm->part[p])[row];
                const float4 pb = reinterpret_cast<const float4*>(sm->part[p])[128 + row];
                const float o0 = pa.x + pb.x + sm->b3[0];
                const float o1 = pa.y + pb.y + sm->b3[1];
                const float o2 = pa.z + pb.z + sm->b3[2];
                const float o3v = pa.w + pb.w + sm->b3[3];
                const float4* s = reinterpret_cast<const float4*>(sm->scal[p] + row * 8);
                const float4 fv = s[0];
                const float4 rv = s[1];
                const float x00 = o0, x01 = 0.5f * (o1 + o2), x11 = o3v;
                const float r00 = rv.x, r01 = rv.y;
                float4 ov;
                ov.x =  r00*x00 + r01*x01 + fv.x;
                ov.y =  r00*x01 + r01*x11 + fv.y;
                ov.z = -r01*x00 + r00*x01 + fv.z;
                ov.w = -r01*x01 + r00*x11 + fv.w;
                reinterpret_cast<float4*>(out)[elem] = ov;
            }
        }
        p ^= 1;
    }
}

extern "C" void kernel_launch(void* const* d_in, const int* in_sizes, int n_in,
                              void* d_out, int out_size)
{
    const float* F  = (const float*)d_in[0];
    const float* W1 = (const float*)d_in[1];
    const float* b1 = (const float*)d_in[2];
    const float* W2 = (const float*)d_in[3];
    const float* b2 = (const float*)d_in[4];
    const float* W3 = (const float*)d_in[5];
    const float* b3 = (const float*)d_in[6];
    float* out = (float*)d_out;

    const int n = in_sizes[0] / 4;   // number of 2x2 matrices

    const size_t smem_bytes = sizeof(SmemT);
    cudaFuncSetAttribute(defcorr_mma,
                         cudaFuncAttributeMaxDynamicSharedMemorySize, (int)smem_bytes);

    defcorr_mma<<<NBLOCKS, NTHREADS, smem_bytes>>>(F, W1, b1, W2, b2, W3, b3, out, n);
}

// round 9
// speedup vs baseline: 1.3058x; 1.0729x over previous
#include <cuda_runtime.h>
#include <cuda_fp16.h>
#include <cstdint>

#define NTHREADS 256
#define NBLOCKS  296

// ---------------- PTX helpers ----------------
__device__ __forceinline__ uint32_t smem_u32(const void* p) {
    uint32_t a;
    asm("{ .reg .u64 t; cvta.to.shared.u64 t, %1; cvt.u32.u64 %0, t; }" : "=r"(a) : "l"(p));
    return a;
}
__device__ __forceinline__ void ldmx2(uint32_t& r0, uint32_t& r1, uint32_t addr) {
    asm volatile("ldmatrix.sync.aligned.m8n8.x2.shared.b16 {%0,%1}, [%2];"
                 : "=r"(r0), "=r"(r1) : "r"(addr));
}
__device__ __forceinline__ void ldmx4(uint32_t& r0, uint32_t& r1, uint32_t& r2, uint32_t& r3,
                                      uint32_t addr) {
    asm volatile("ldmatrix.sync.aligned.m8n8.x4.shared.b16 {%0,%1,%2,%3}, [%4];"
                 : "=r"(r0), "=r"(r1), "=r"(r2), "=r"(r3) : "r"(addr));
}
// fp16-accumulator MMAs (double-rate tensor path; D regs are packed half2 in
// exactly the A-fragment layout of the next m16n8k16 MMA).
__device__ __forceinline__ void mma_k8_f16(uint32_t& d0, uint32_t& d1,
                                           uint32_t a0, uint32_t a1, uint32_t b0,
                                           uint32_t zero) {
    asm volatile("mma.sync.aligned.m16n8k8.row.col.f16.f16.f16.f16 "
                 "{%0,%1}, {%2,%3}, {%4}, {%5,%5};"
                 : "=r"(d0), "=r"(d1)
                 : "r"(a0), "r"(a1), "r"(b0), "r"(zero));
}
__device__ __forceinline__ void mma_k16_f16(uint32_t& d0, uint32_t& d1,
                                            uint32_t a0, uint32_t a1, uint32_t a2,
                                            uint32_t a3, uint32_t b0, uint32_t b1) {
    asm volatile("mma.sync.aligned.m16n8k16.row.col.f16.f16.f16.f16 "
                 "{%0,%1}, {%2,%3,%4,%5}, {%6,%7}, {%0,%1};"
                 : "+r"(d0), "+r"(d1)
                 : "r"(a0), "r"(a1), "r"(a2), "r"(a3), "r"(b0), "r"(b1));
}
__device__ __forceinline__ void mma_k16(float* d, uint32_t a0, uint32_t a1, uint32_t a2,
                                        uint32_t a3, uint32_t b0, uint32_t b1) {
    asm volatile("mma.sync.aligned.m16n8k16.row.col.f32.f16.f16.f32 "
                 "{%0,%1,%2,%3}, {%4,%5,%6,%7}, {%8,%9}, {%0,%1,%2,%3};"
                 : "+f"(d[0]), "+f"(d[1]), "+f"(d[2]), "+f"(d[3])
                 : "r"(a0), "r"(a1), "r"(a2), "r"(a3), "r"(b0), "r"(b1));
}
__device__ __forceinline__ uint32_t pack_h2(float x, float y) {
    __half2 h = __floats2half2_rn(x, y);          // low half = x
    return *reinterpret_cast<uint32_t*>(&h);
}
__device__ __forceinline__ uint32_t relu_h2(uint32_t u) {
    __half2 h = *reinterpret_cast<__half2*>(&u);
    __half2 z = __floats2half2_rn(0.f, 0.f);
    __half2 r = __hmax2(h, z);
    return *reinterpret_cast<uint32_t*>(&r);
}

// ---------------- shared memory (dynamic, ~58 KB) ----------------
struct SmemT {
    __align__(16) uint8_t w2t[128 * 256];      // W2^T [n][k] half, swizzled (32 KB)
    __align__(16) __half  w1t[128 * 8];        // W1^T (+b1 in k7)            (2 KB)
    __align__(16) __half  inv[2][128 * 8];     // invariants, double-buffered (4 KB)
    __align__(16) float   scal[2][128 * 8];    // {a,b,c,d,r00,r01}, dbl-buf  (8 KB)
    __align__(16) float   w3[128 * 4];         // staging for W3 frag preload (2 KB)
    __align__(16) float   part[2][2 * 128 * 4];// layer-3 partials, dbl-buf   (8 KB)
    float b2[128];
    float b3[4];
};

__device__ __forceinline__ void compute_inv(SmemT* sm, int p, int row, float4 f) {
    const float a = f.x, b = f.y, c = f.z, d = f.w;
    const float t0 = a + d, t1 = b - c, t2 = a - d, t3 = b + c;
    const float pp = sqrtf(t0*t0 + t1*t1);
    const float qq = sqrtf(t2*t2 + t3*t3);
    const float i0 = 0.5f*(pp + qq) - 1.f;
    const float i1 = 0.5f*fabsf(pp - qq) - 1.f;
    const float i2 = a*a + c*c - 1.f;
    const float i3 = a*b + c*d;          // == i4
    const float i5 = b*b + d*d - 1.f;
    const float i6 = a*d - b*c - 1.f;
    const float rp  = 1.f / pp;
    const float r00 = t0 * rp, r01 = t1 * rp;

    uint4 u;
    u.x = pack_h2(i0, i1);
    u.y = pack_h2(i2, i3);
    u.z = pack_h2(i3, i5);
    u.w = pack_h2(i6, 1.0f);             // k7 = 1.0 (bias input)
    reinterpret_cast<uint4*>(sm->inv[p])[row] = u;

    float4* s = reinterpret_cast<float4*>(sm->scal[p] + row * 8);
    s[0] = f;
    s[1] = make_float4(r00, r01, 0.f, 0.f);
}

__global__ __launch_bounds__(NTHREADS, 2)
void defcorr_mma(const float* __restrict__ Fg,
                 const float* __restrict__ W1, const float* __restrict__ b1,
                 const float* __restrict__ W2, const float* __restrict__ b2,
                 const float* __restrict__ W3, const float* __restrict__ b3,
                 float* __restrict__ out, int n)
{
    extern __shared__ char dsm[];
    SmemT* sm = reinterpret_cast<SmemT*>(dsm);

    const int tid  = threadIdx.x;
    const int lane = tid & 31;
    const int warp = tid >> 5;
    const int rg   = warp >> 1;               // row group: 32 rows each
    const int ch   = warp & 1;                // column half: 64 cols each
    const int warpm0 = rg * 32;

    // ---------- stage weights (once) ----------
    for (int i = tid; i < 128 * 128; i += NTHREADS) {
        const int nn = i >> 7, k = i & 127;
        const int c  = k >> 3;
        const int cs = (c & 8) | ((c ^ nn) & 7);
        const uint32_t off = (uint32_t)nn * 256u + (uint32_t)cs * 16u + (uint32_t)(k & 7) * 2u;
        *reinterpret_cast<__half*>(sm->w2t + off) = __float2half(W2[k * 128 + nn]);
    }
    for (int i = tid; i < 128 * 8; i += NTHREADS) {
        const int nn = i >> 3, k = i & 7;
        sm->w1t[i] = __float2half(k < 7 ? W1[k * 128 + nn] : b1[nn]);
    }
    for (int i = tid; i < 128 * 4; i += NTHREADS) sm->w3[i] = W3[i];
    for (int i = tid; i < 128;     i += NTHREADS) sm->b2[i] = b2[i];
    if (tid < 4) sm->b3[tid] = b3[tid];

    const uint32_t uW2  = smem_u32(sm->w2t);
    const uint32_t uW1  = smem_u32(sm->w1t);
    const uint32_t uInv = smem_u32(sm->inv[0]);

    // per-lane layer-2 ldmatrix address components
    const int rowPart = ((lane >> 4) << 3) | (lane & 7);
    const int kSel    = (lane >> 3) & 1;
    const uint32_t bAddrBase  = uW2 + (uint32_t)rowPart * 256u + (uint32_t)(ch * 4) * 4096u;
    const uint32_t w1AddrBase = uW1 + (uint32_t)(lane & 15) * 16u;

    __syncthreads();   // weights staged

    // ---------- preload persistent fragments ----------
    // W1 B-fragments: 8 k-steps x 2 regs (constant all kernel)
    uint32_t w1f[8][2];
    #pragma unroll
    for (int s = 0; s < 8; ++s)
        ldmx2(w1f[s][0], w1f[s][1], w1AddrBase + (uint32_t)(s * 16) * 16u);

    // W3 B-fragments: n 0..3 real, 4..7 zero pad; k global = ch*64 + s3*16 + klocal
    uint32_t w3b[4][2];
    {
        const int nn = lane >> 2;
        #pragma unroll
        for (int s3 = 0; s3 < 4; ++s3) {
            const int k0 = ch*64 + s3*16 + (lane & 3)*2;
            if (nn < 4) {
                w3b[s3][0] = pack_h2(sm->w3[k0*4 + nn],       sm->w3[(k0+1)*4 + nn]);
                w3b[s3][1] = pack_h2(sm->w3[(k0+8)*4 + nn],   sm->w3[(k0+9)*4 + nn]);
            } else {
                w3b[s3][0] = 0u; w3b[s3][1] = 0u;
            }
        }
    }

    // b2 packed per n-pair (persistent, 8 regs) — init value for d2 f16 accumulators
    uint32_t b2pk[8];
    #pragma unroll
    for (int jl = 0; jl < 8; ++jl) {
        const int n0 = ch*64 + jl*8 + (lane & 3)*2;
        b2pk[jl] = pack_h2(sm->b2[n0], sm->b2[n0 + 1]);
    }

    const int ntiles = (n + 127) >> 7;

    // ---------- prologue: invariants for first tile into buffer 0 ----------
    if (tid < 128 && blockIdx.x < ntiles) {
        const int elem = blockIdx.x * 128 + tid;
        float4 f = make_float4(1.f, 0.f, 0.f, 1.f);
        if (elem < n) f = reinterpret_cast<const float4*>(Fg)[elem];
        compute_inv(sm, 0, tid, f);
    }
    __syncthreads();

    const uint32_t zero = 0u;
    int p = 0;
    for (int tile = blockIdx.x; tile < ntiles; tile += gridDim.x) {
        const int ntile = tile + gridDim.x;

        // ---------- prefetch next tile's F early (hides LDG behind MMA) ----------
        float4 fnx = make_float4(1.f, 0.f, 0.f, 1.f);
        if (tid < 128 && ntile < ntiles) {
            const int e = ntile * 128 + tid;
            if (e < n) fnx = reinterpret_cast<const float4*>(Fg)[e];
        }

        // ---------- A-inputs for layer 1 (reads inv[p]) ----------
        const uint32_t uInvP = uInv + (uint32_t)p * 2048u;
        uint32_t ai[2][2];
        ldmx2(ai[0][0], ai[0][1], uInvP + (uint32_t)(warpm0      + (lane & 15)) * 16u);
        ldmx2(ai[1][0], ai[1][1], uInvP + (uint32_t)(warpm0 + 16 + (lane & 15)) * 16u);

        // ---------- init layer-2 f16 accumulators with b2 ----------
        uint32_t d2[16][2];                 // [t*8 + jl][{rows r, rows r+8}]
        #pragma unroll
        for (int jl = 0; jl < 8; ++jl) {
            d2[jl][0]   = b2pk[jl]; d2[jl][1]   = b2pk[jl];
            d2[8+jl][0] = b2pk[jl]; d2[8+jl][1] = b2pk[jl];
        }

        // ---------- fused layer1 + layer2 (both f16 accum), per k-step ----------
        #pragma unroll
        for (int s = 0; s < 8; ++s) {
            uint32_t pk[2][4];
            #pragma unroll
            for (int t = 0; t < 2; ++t) {
                uint32_t u0, u1, u2, u3;
                mma_k8_f16(u0, u1, ai[t][0], ai[t][1], w1f[s][0], zero);
                mma_k8_f16(u2, u3, ai[t][0], ai[t][1], w1f[s][1], zero);
                pk[t][0] = relu_h2(u0);
                pk[t][1] = relu_h2(u1);
                pk[t][2] = relu_h2(u2);
                pk[t][3] = relu_h2(u3);
            }

            const int c  = 2*s + kSel;
            const int cs = (c & 8) | ((c ^ rowPart) & 7);
            #pragma unroll
            for (int j = 0; j < 4; ++j) {
                uint32_t br0, br1, br2, br3;
                ldmx4(br0, br1, br2, br3,
                      bAddrBase + (uint32_t)(j * 4096) + (uint32_t)cs * 16u);
                mma_k16_f16(d2[2*j][0],     d2[2*j][1],
                            pk[0][0], pk[0][1], pk[0][2], pk[0][3], br0, br1);
                mma_k16_f16(d2[2*j+1][0],   d2[2*j+1][1],
                            pk[0][0], pk[0][1], pk[0][2], pk[0][3], br2, br3);
                mma_k16_f16(d2[8+2*j][0],   d2[8+2*j][1],
                            pk[1][0], pk[1][1], pk[1][2], pk[1][3], br0, br1);
                mma_k16_f16(d2[8+2*j+1][0], d2[8+2*j+1][1],
                            pk[1][0], pk[1][1], pk[1][2], pk[1][3], br2, br3);
            }
        }

        // ---------- layer 3 as MMA (fp32 accum): relu(d2) already packed ----------
        float o3[2][4];
        o3[0][0]=o3[0][1]=o3[0][2]=o3[0][3]=0.f;
        o3[1][0]=o3[1][1]=o3[1][2]=o3[1][3]=0.f;
        #pragma unroll
        for (int s3 = 0; s3 < 4; ++s3) {
            const int j0 = 2*s3, j1 = 2*s3 + 1;
            #pragma unroll
            for (int t = 0; t < 2; ++t) {
                const uint32_t a0 = relu_h2(d2[t*8 + j0][0]);
                const uint32_t a1 = relu_h2(d2[t*8 + j0][1]);
                const uint32_t a2 = relu_h2(d2[t*8 + j1][0]);
                const uint32_t a3 = relu_h2(d2[t*8 + j1][1]);
                mma_k16(o3[t], a0, a1, a2, a3, w3b[s3][0], w3b[s3][1]);
            }
        }

        // ---------- write layer-3 partials (only lanes with n<4 hold real data) ----------
        if ((lane & 3) < 2) {
            #pragma unroll
            for (int t = 0; t < 2; ++t) {
                const int row0 = warpm0 + t*16 + (lane >> 2);
                float2* p0 = reinterpret_cast<float2*>(
                    sm->part[p] + (ch*128 + row0) * 4) + (lane & 3);
                float2* p1 = reinterpret_cast<float2*>(
                    sm->part[p] + (ch*128 + row0 + 8) * 4) + (lane & 3);
                *p0 = make_float2(o3[t][0], o3[t][1]);
                *p1 = make_float2(o3[t][2], o3[t][3]);
            }
        }

        // ---------- invariants for next tile (other buffer; overlaps MMA stragglers) ----------
        if (tid < 128 && ntile < ntiles) compute_inv(sm, p ^ 1, tid, fnx);

        __syncthreads();   // single barrier: covers part[p] and inv/scal[p^1]

        // ---------- final epilogue: combine halves, rotate, store ----------
        if (tid < 128) {
            const int row  = tid;
            const int elem = tile * 128 + row;
            if (elem < n) {
                const float4 pa = reinterpret_cast<const float4*>(sm->part[p])[row];
                const float4 pb = reinterpret_cast<const float4*>(sm->part[p])[128 + row];
                const float o0 = pa.x + pb.x + sm->b3[0];
                const float o1 = pa.y + pb.y + sm->b3[1];
                const float o2 = pa.z + pb.z + sm->b3[2];
                const float o3v = pa.w + pb.w + sm->b3[3];
                const float4* s = reinterpret_cast<const float4*>(sm->scal[p] + row * 8);
                const float4 fv = s[0];
                const float4 rv = s[1];
                const float x00 = o0, x01 = 0.5f * (o1 + o2), x11 = o3v;
                const float r00 = rv.x, r01 = rv.y;
                float4 ov;
                ov.x =  r00*x00 + r01*x01 + fv.x;
                ov.y =  r00*x01 + r01*x11 + fv.y;
                ov.z = -r01*x00 + r00*x01 + fv.z;
                ov.w = -r01*x01 + r00*x11 + fv.w;
                reinterpret_cast<float4*>(out)[elem] = ov;
            }
        }
        p ^= 1;
    }
}

extern "C" void kernel_launch(void* const* d_in, const int* in_sizes, int n_in,
                              void* d_out, int out_size)
{
    const float* F  = (const float*)d_in[0];
    const float* W1 = (const float*)d_in[1];
    const float* b1 = (const float*)d_in[2];
    const float* W2 = (const float*)d_in[3];
    const float* b2 = (const float*)d_in[4];
    const float* W3 = (const float*)d_in[5];
    const float* b3 = (const float*)d_in[6];
    float* out = (float*)d_out;

    const int n = in_sizes[0] / 4;   // number of 2x2 matrices

    const size_t smem_bytes = sizeof(SmemT);
    cudaFuncSetAttribute(defcorr_mma,
                         cudaFuncAttributeMaxDynamicSharedMemorySize, (int)smem_bytes);

    defcorr_mma<<<NBLOCKS, NTHREADS, smem_bytes>>>(F, W1, b1, W2, b2, W3, b3, out, n);
}